// round 11
// baseline (speedup 1.0000x reference)
#include <cuda_runtime.h>
#include <cuda_fp16.h>
#include <cstdint>

// ---------------------------------------------------------------------------
// QuantizedLMHead (sm_103 baseline ISA):
//   prep:  Wh = fp16((lx*lw)*Z_w)              -> g_Wx  [2048, 32000]
//          x -> xh + 2^-11*xl'  (scaled fp16 residual)
//          U -> Uh + 2^-11*Ul'  (scaled fp16 residual)
//   GEMM1: acc = xl'@Uh + xh@Ul'; acc *= 2^-11; acc += xh@Uh
//          + nearest-codebook quantize epilogue -> fp16 g_Aq
//   GEMM2: logits = A @ Wh (mma.sync m16n8k16, fp32 acc, K=2048)
//
// R10: scheduling only — cp.async burst issued after ks=0 (overlaps tensor
// work), GEMM1 pass loop split (no per-iter branch), streaming C stores.
// ---------------------------------------------------------------------------

#define D_DIM 2048
#define V_DIM 32000
#define N_TOK 4096
#define RES_SCALE 2048.0f
#define RES_INV   (1.0f / 2048.0f)

__device__ __align__(256) __half g_Aq[(size_t)N_TOK * D_DIM];   // 16.8 MB
__device__ __align__(256) __half g_Wx[(size_t)D_DIM * V_DIM];   // 131 MB
__device__ __align__(256) __half g_xh[(size_t)N_TOK * D_DIM];
__device__ __align__(256) __half g_xl[(size_t)N_TOK * D_DIM];   // scaled 2^11
__device__ __align__(256) __half g_Uh[(size_t)D_DIM * D_DIM];
__device__ __align__(256) __half g_Ul[(size_t)D_DIM * D_DIM];   // scaled 2^11

// ---------------- PTX helpers ----------------------------------------------
__device__ __forceinline__ uint32_t smem_u32(const void* p) {
    uint32_t a;
    asm("{ .reg .u64 t; cvta.to.shared.u64 t, %1; cvt.u32.u64 %0, t; }" : "=r"(a) : "l"(p));
    return a;
}
__device__ __forceinline__ void cp16(uint32_t dst, const void* src) {
    asm volatile("cp.async.cg.shared.global [%0], [%1], 16;" :: "r"(dst), "l"(src));
}
#define CP_COMMIT() asm volatile("cp.async.commit_group;" ::: "memory")
#define CP_WAIT2()  asm volatile("cp.async.wait_group 2;" ::: "memory")

__device__ __forceinline__ void ldsm4(uint32_t* r, uint32_t addr) {
    asm volatile("ldmatrix.sync.aligned.m8n8.x4.shared.b16 {%0,%1,%2,%3}, [%4];"
                 : "=r"(r[0]), "=r"(r[1]), "=r"(r[2]), "=r"(r[3]) : "r"(addr));
}
__device__ __forceinline__ void ldsm4t(uint32_t* r, uint32_t addr) {
    asm volatile("ldmatrix.sync.aligned.m8n8.x4.trans.shared.b16 {%0,%1,%2,%3}, [%4];"
                 : "=r"(r[0]), "=r"(r[1]), "=r"(r[2]), "=r"(r[3]) : "r"(addr));
}
__device__ __forceinline__ void mma16816(float* c, const uint32_t* a, uint32_t b0, uint32_t b1) {
    asm volatile("mma.sync.aligned.m16n8k16.row.col.f32.f16.f16.f32 "
                 "{%0,%1,%2,%3}, {%4,%5,%6,%7}, {%8,%9}, {%0,%1,%2,%3};"
                 : "+f"(c[0]), "+f"(c[1]), "+f"(c[2]), "+f"(c[3])
                 : "r"(a[0]), "r"(a[1]), "r"(a[2]), "r"(a[3]), "r"(b0), "r"(b1));
}
__device__ __forceinline__ void stcs2(float* p, float2 v) {
    asm volatile("st.global.cs.v2.f32 [%0], {%1, %2};" :: "l"(p), "f"(v.x), "f"(v.y) : "memory");
}

// ---------------------------------------------------------------------------
// Prep kernels (unchanged)
// ---------------------------------------------------------------------------
__global__ __launch_bounds__(256)
void wprep_kernel(const float* __restrict__ Zw, const float* __restrict__ lx,
                  const float* __restrict__ lw)
{
    const int idx = blockIdx.x * 256 + threadIdx.x;
    const int k   = idx / (V_DIM / 4);
    const int v4  = idx % (V_DIM / 4);
    const float coeff = __ldg(lx + k) * __ldg(lw + k);
    float4 w = *reinterpret_cast<const float4*>(Zw + (size_t)k * V_DIM + v4 * 4);
    __half h[4];
    h[0] = __float2half(coeff * w.x);
    h[1] = __float2half(coeff * w.y);
    h[2] = __float2half(coeff * w.z);
    h[3] = __float2half(coeff * w.w);
    *reinterpret_cast<uint2*>(g_Wx + (size_t)k * V_DIM + v4 * 4) =
        *reinterpret_cast<uint2*>(h);
}

template <int WHICH>   // 0: x -> g_xh/g_xl, 1: U -> g_Uh/g_Ul
__global__ __launch_bounds__(256)
void split_kernel(const float* __restrict__ src)
{
    __half* hi = (WHICH == 0) ? g_xh : g_Uh;
    __half* lo = (WHICH == 0) ? g_xl : g_Ul;
    const size_t i4 = ((size_t)blockIdx.x * 256 + threadIdx.x) * 4;
    float4 v = *reinterpret_cast<const float4*>(src + i4);
    __half h[4], l[4];
    h[0] = __float2half(v.x); l[0] = __float2half((v.x - __half2float(h[0])) * RES_SCALE);
    h[1] = __float2half(v.y); l[1] = __float2half((v.y - __half2float(h[1])) * RES_SCALE);
    h[2] = __float2half(v.z); l[2] = __float2half((v.z - __half2float(h[2])) * RES_SCALE);
    h[3] = __float2half(v.w); l[3] = __float2half((v.w - __half2float(h[3])) * RES_SCALE);
    *reinterpret_cast<uint2*>(hi + i4) = *reinterpret_cast<uint2*>(h);
    *reinterpret_cast<uint2*>(lo + i4) = *reinterpret_cast<uint2*>(l);
}

// ---------------------------------------------------------------------------
// GEMM tiling: 128(M)x256(N) CTA tile, BK=64, 4-stage cp.async,
// 512 threads = 16 warps as 2(m)x8(n), warp tile 64x32.
// ---------------------------------------------------------------------------
#define BKK 64
#define STAGES 4
#define A_ROW_B 144                     // 64 fp16 + 8 pad
#define B_ROW_B 528                     // 256 fp16 + 8 pad (odd * 16B)
#define A_STG (128 * A_ROW_B)           // 18432
#define B_STG (64 * B_ROW_B)            // 33792
#define STG_B (A_STG + B_STG)           // 52224
#define SMEM_MMA (STAGES * STG_B)       // 208896
#define NTHREADS 512

// One kt step: ks=0, then the cp.async burst, then ks=1..3.
#define KT_BODY(SA, SBB, LOADS)                                               \
    {                                                                         \
        uint32_t a[4][4], b[2][4];                                            \
        /* ks = 0 */                                                          \
        _Pragma("unroll")                                                     \
        for (int mi = 0; mi < 4; ++mi)                                        \
            ldsm4(a[mi], (SA) + (a_row_l + mi * 16) * A_ROW_B + a_k_l * 2);   \
        _Pragma("unroll")                                                     \
        for (int ni2 = 0; ni2 < 2; ++ni2)                                     \
            ldsm4t(b[ni2], (SBB) + b_row_l * B_ROW_B + (b_col_l + ni2 * 16) * 2); \
        _Pragma("unroll")                                                     \
        for (int mi = 0; mi < 4; ++mi)                                        \
            _Pragma("unroll")                                                 \
            for (int ni = 0; ni < 4; ++ni)                                    \
                mma16816(acc[mi][ni], a[mi], b[ni >> 1][2 * (ni & 1)],        \
                         b[ni >> 1][2 * (ni & 1) + 1]);                       \
        LOADS;                                                                \
        _Pragma("unroll")                                                     \
        for (int ks = 1; ks < 4; ++ks) {                                      \
            _Pragma("unroll")                                                 \
            for (int mi = 0; mi < 4; ++mi)                                    \
                ldsm4(a[mi], (SA) + (a_row_l + mi * 16) * A_ROW_B + (a_k_l + ks * 16) * 2); \
            _Pragma("unroll")                                                 \
            for (int ni2 = 0; ni2 < 2; ++ni2)                                 \
                ldsm4t(b[ni2], (SBB) + (b_row_l + ks * 16) * B_ROW_B + (b_col_l + ni2 * 16) * 2); \
            _Pragma("unroll")                                                 \
            for (int mi = 0; mi < 4; ++mi)                                    \
                _Pragma("unroll")                                             \
                for (int ni = 0; ni < 4; ++ni)                                \
                    mma16816(acc[mi][ni], a[mi], b[ni >> 1][2 * (ni & 1)],    \
                             b[ni >> 1][2 * (ni & 1) + 1]);                   \
        }                                                                     \
    }

// ---------------------------------------------------------------------------
// GEMM1 — scaled-residual 3-pass + quantize -> g_Aq.
// grid (N_TOK/128, D_DIM/256) = (32, 8). K_ext = 3*2048.
// ---------------------------------------------------------------------------
__global__ __launch_bounds__(NTHREADS, 1)
void gemm1_mma_kernel(const float* __restrict__ lx, const float* __restrict__ cb)
{
    extern __shared__ __align__(128) unsigned char sm1[];
    const uint32_t sb = smem_u32(sm1);
    const int tid  = threadIdx.x;
    const int lane = tid & 31;
    const int wid  = tid >> 5;
    const int wm   = wid >> 3;          // 0..1
    const int wn   = wid & 7;           // 0..7
    const int m0   = blockIdx.x * 128;
    const int n0   = blockIdx.y * 256;

    float acc[4][4][4];
    #pragma unroll
    for (int mi = 0; mi < 4; ++mi)
        #pragma unroll
        for (int ni = 0; ni < 4; ++ni)
            #pragma unroll
            for (int r = 0; r < 4; ++r) acc[mi][ni][r] = 0.0f;

    auto load_stage = [&](int kt, int slot) {
        const int p  = kt >> 5;            // pass: 0=lh, 1=hl, 2=hh
        const int kb = (kt & 31) * BKK;
        const __half* Ab = (p == 0) ? g_xl : g_xh;
        const __half* Bb = (p == 1) ? g_Ul : g_Uh;
        const uint32_t sa  = sb + slot * STG_B;
        const uint32_t sbB = sa + A_STG;
        #pragma unroll
        for (int i = 0; i < 2; ++i) {
            int cc = tid + i * NTHREADS;
            int row = cc >> 3, col = (cc & 7) * 8;
            cp16(sa + row * A_ROW_B + col * 2,
                 Ab + (size_t)(m0 + row) * D_DIM + kb + col);
        }
        #pragma unroll
        for (int i = 0; i < 4; ++i) {
            int cc = tid + i * NTHREADS;
            int row = cc >> 5, col = (cc & 31) * 8;
            cp16(sbB + row * B_ROW_B + col * 2,
                 Bb + (size_t)(kb + row) * D_DIM + n0 + col);
        }
        CP_COMMIT();
    };

    const int KT = 3 * (D_DIM / BKK);    // 96
    load_stage(0, 0);
    load_stage(1, 1);
    load_stage(2, 2);

    const int a_row_l = wm * 64 + (lane & 15);
    const int a_k_l   = (lane >> 4) * 8;
    const int b_row_l = (lane & 7) + ((lane >> 3) & 1) * 8;
    const int b_col_l = wn * 32 + ((lane >> 4) & 1) * 8;

    // correction passes: kt 0..63 (kt+3 always < 96 -> unconditional prefetch)
    for (int kt = 0; kt < 64; ++kt) {
        CP_WAIT2();
        __syncthreads();
        const int slot = kt & (STAGES - 1);
        const uint32_t sa  = sb + slot * STG_B;
        const uint32_t sbb = sa + A_STG;
        KT_BODY(sa, sbb, load_stage(kt + 3, (kt + 3) & (STAGES - 1)));
    }

    // acc holds 2^11*(lh+hl): rescale once
    #pragma unroll
    for (int mi = 0; mi < 4; ++mi)
        #pragma unroll
        for (int ni = 0; ni < 4; ++ni)
            #pragma unroll
            for (int r = 0; r < 4; ++r)
                acc[mi][ni][r] *= RES_INV;

    // hh pass: kt 64..95
    for (int kt = 64; kt < KT; ++kt) {
        CP_WAIT2();
        __syncthreads();
        const int slot = kt & (STAGES - 1);
        const uint32_t sa  = sb + slot * STG_B;
        const uint32_t sbb = sa + A_STG;
        if (kt + 3 < KT) {
            KT_BODY(sa, sbb, load_stage(kt + 3, (kt + 3) & (STAGES - 1)));
        } else {
            KT_BODY(sa, sbb, CP_COMMIT());
        }
    }

    // epilogue: quantize s -> codebook value (tie -> lower index), store fp16
    float c[16];
    #pragma unroll
    for (int t = 0; t < 16; ++t) c[t] = cb[t];

    #pragma unroll
    for (int ni = 0; ni < 4; ++ni) {
        const int c0 = n0 + wn * 32 + ni * 8 + (lane & 3) * 2;
        float l0 = lx[c0], l1 = lx[c0 + 1];
        float s0 = (fabsf(l0) < 1e-8f) ? 1e-8f : l0;
        float s1 = (fabsf(l1) < 1e-8f) ? 1e-8f : l1;
        #pragma unroll
        for (int mi = 0; mi < 4; ++mi) {
            const int r0 = m0 + wm * 64 + mi * 16 + (lane >> 2);
            #pragma unroll
            for (int half_i = 0; half_i < 2; ++half_i) {
                float z0 = acc[mi][ni][2 * half_i]     / s0;
                float z1 = acc[mi][ni][2 * half_i + 1] / s1;
                float q0 = c[0], q1 = c[0];
                #pragma unroll
                for (int t = 0; t < 15; ++t) {
                    float mid = 0.5f * (c[t] + c[t + 1]);
                    q0 = (z0 > mid) ? c[t + 1] : q0;
                    q1 = (z1 > mid) ? c[t + 1] : q1;
                }
                __half2 hv = __halves2half2(__float2half(q0), __float2half(q1));
                *reinterpret_cast<uint32_t*>(
                    &g_Aq[(size_t)(r0 + 8 * half_i) * D_DIM + c0]) =
                    *reinterpret_cast<uint32_t*>(&hv);
            }
        }
    }
}

// ---------------------------------------------------------------------------
// GEMM2 — logits = A @ Wh. grid (N_TOK/128, V_DIM/256). K = 2048.
// ---------------------------------------------------------------------------
__global__ __launch_bounds__(NTHREADS, 1)
void gemm2_mma_kernel(float* __restrict__ C)
{
    extern __shared__ __align__(128) unsigned char sm2[];
    const uint32_t sb = smem_u32(sm2);
    const int tid  = threadIdx.x;
    const int lane = tid & 31;
    const int wid  = tid >> 5;
    const int wm   = wid >> 3;
    const int wn   = wid & 7;
    const int m0   = blockIdx.x * 128;
    const int n0   = blockIdx.y * 256;

    float acc[4][4][4];
    #pragma unroll
    for (int mi = 0; mi < 4; ++mi)
        #pragma unroll
        for (int ni = 0; ni < 4; ++ni)
            #pragma unroll
            for (int r = 0; r < 4; ++r) acc[mi][ni][r] = 0.0f;

    auto load_stage = [&](int kt, int slot) {
        const int kb = kt * BKK;
        const uint32_t sa  = sb + slot * STG_B;
        const uint32_t sbB = sa + A_STG;
        #pragma unroll
        for (int i = 0; i < 2; ++i) {
            int cc = tid + i * NTHREADS;
            int row = cc >> 3, col = (cc & 7) * 8;
            cp16(sa + row * A_ROW_B + col * 2,
                 g_Aq + (size_t)(m0 + row) * D_DIM + kb + col);
        }
        #pragma unroll
        for (int i = 0; i < 4; ++i) {
            int cc = tid + i * NTHREADS;
            int row = cc >> 5, col = (cc & 31) * 8;
            cp16(sbB + row * B_ROW_B + col * 2,
                 g_Wx + (size_t)(kb + row) * V_DIM + n0 + col);
        }
        CP_COMMIT();
    };

    const int KT = D_DIM / BKK;     // 32
    load_stage(0, 0);
    load_stage(1, 1);
    load_stage(2, 2);

    const int a_row_l = wm * 64 + (lane & 15);
    const int a_k_l   = (lane >> 4) * 8;
    const int b_row_l = (lane & 7) + ((lane >> 3) & 1) * 8;
    const int b_col_l = wn * 32 + ((lane >> 4) & 1) * 8;

    for (int kt = 0; kt < KT; ++kt) {
        CP_WAIT2();
        __syncthreads();
        const int slot = kt & (STAGES - 1);
        const uint32_t sa  = sb + slot * STG_B;
        const uint32_t sbb = sa + A_STG;
        if (kt + 3 < KT) {
            KT_BODY(sa, sbb, load_stage(kt + 3, (kt + 3) & (STAGES - 1)));
        } else {
            KT_BODY(sa, sbb, CP_COMMIT());
        }
    }

    // epilogue: streaming stores (write-once data; keep A/B resident in L2)
    #pragma unroll
    for (int mi = 0; mi < 4; ++mi) {
        const int row = m0 + wm * 64 + mi * 16 + (lane >> 2);
        #pragma unroll
        for (int ni = 0; ni < 4; ++ni) {
            const int col = n0 + wn * 32 + ni * 8 + (lane & 3) * 2;
            stcs2(C + (size_t)row * V_DIM + col,
                  make_float2(acc[mi][ni][0], acc[mi][ni][1]));
            stcs2(C + (size_t)(row + 8) * V_DIM + col,
                  make_float2(acc[mi][ni][2], acc[mi][ni][3]));
        }
    }
}

// ---------------------------------------------------------------------------
extern "C" void kernel_launch(void* const* d_in, const int* in_sizes, int n_in,
                              void* d_out, int out_size)
{
    const float* x  = (const float*)d_in[0];
    const float* U  = (const float*)d_in[1];
    const float* lx = (const float*)d_in[2];
    const float* lw = (const float*)d_in[3];
    const float* Zw = (const float*)d_in[4];
    const float* cb = (const float*)d_in[5];
    float* out = (float*)d_out;

    cudaFuncSetAttribute(gemm1_mma_kernel,
                         cudaFuncAttributeMaxDynamicSharedMemorySize, SMEM_MMA);
    cudaFuncSetAttribute(gemm2_mma_kernel,
                         cudaFuncAttributeMaxDynamicSharedMemorySize, SMEM_MMA);

    // prep
    wprep_kernel<<<(D_DIM * V_DIM / 4) / 256, 256>>>(Zw, lx, lw);
    split_kernel<0><<<((size_t)N_TOK * D_DIM / 4) / 256, 256>>>(x);
    split_kernel<1><<<((size_t)D_DIM * D_DIM / 4) / 256, 256>>>(U);

    // GEMM1 (scaled-residual 3-pass) + quantize -> g_Aq
    gemm1_mma_kernel<<<dim3(N_TOK / 128, D_DIM / 256), NTHREADS, SMEM_MMA>>>(lx, cb);

    // GEMM2 -> logits
    gemm2_mma_kernel<<<dim3(N_TOK / 128, V_DIM / 256), NTHREADS, SMEM_MMA>>>(out);
}

// round 12
// speedup vs baseline: 1.1133x; 1.1133x over previous
#include <cuda_runtime.h>
#include <cuda_fp16.h>
#include <cstdint>

// ---------------------------------------------------------------------------
// QuantizedLMHead (sm_103 baseline ISA):
//   prep:  Wh = fp16((lx*lw)*Z_w)              -> g_Wx  [2048, 32000]
//          x -> xh + 2^-11*xl'  (scaled fp16 residual)
//          U -> Uh + 2^-11*Ul'  (scaled fp16 residual)
//   GEMM1: acc = xl'@Uh + xh@Ul'; acc *= 2^-11; acc += xh@Uh
//          + nearest-codebook quantize epilogue -> fp16 g_Aq
//   GEMM2: logits = A @ Wh (mma.sync m16n8k16, fp32 acc, K=2048)
//
// R11: revert R10's regressions (st.cs stores, mid-loop load reorder).
// Single change vs R9: 128x128 CTA tiles @ 256 threads, 3-stage, 2 CTAs/SM
// (two independent barrier domains per SM to fill sync/wait gaps).
// ---------------------------------------------------------------------------

#define D_DIM 2048
#define V_DIM 32000
#define N_TOK 4096
#define RES_SCALE 2048.0f
#define RES_INV   (1.0f / 2048.0f)

__device__ __align__(256) __half g_Aq[(size_t)N_TOK * D_DIM];   // 16.8 MB
__device__ __align__(256) __half g_Wx[(size_t)D_DIM * V_DIM];   // 131 MB
__device__ __align__(256) __half g_xh[(size_t)N_TOK * D_DIM];
__device__ __align__(256) __half g_xl[(size_t)N_TOK * D_DIM];   // scaled 2^11
__device__ __align__(256) __half g_Uh[(size_t)D_DIM * D_DIM];
__device__ __align__(256) __half g_Ul[(size_t)D_DIM * D_DIM];   // scaled 2^11

// ---------------- PTX helpers ----------------------------------------------
__device__ __forceinline__ uint32_t smem_u32(const void* p) {
    uint32_t a;
    asm("{ .reg .u64 t; cvta.to.shared.u64 t, %1; cvt.u32.u64 %0, t; }" : "=r"(a) : "l"(p));
    return a;
}
__device__ __forceinline__ void cp16(uint32_t dst, const void* src) {
    asm volatile("cp.async.cg.shared.global [%0], [%1], 16;" :: "r"(dst), "l"(src));
}
#define CP_COMMIT() asm volatile("cp.async.commit_group;" ::: "memory")
#define CP_WAIT1()  asm volatile("cp.async.wait_group 1;" ::: "memory")

__device__ __forceinline__ void ldsm4(uint32_t* r, uint32_t addr) {
    asm volatile("ldmatrix.sync.aligned.m8n8.x4.shared.b16 {%0,%1,%2,%3}, [%4];"
                 : "=r"(r[0]), "=r"(r[1]), "=r"(r[2]), "=r"(r[3]) : "r"(addr));
}
__device__ __forceinline__ void ldsm4t(uint32_t* r, uint32_t addr) {
    asm volatile("ldmatrix.sync.aligned.m8n8.x4.trans.shared.b16 {%0,%1,%2,%3}, [%4];"
                 : "=r"(r[0]), "=r"(r[1]), "=r"(r[2]), "=r"(r[3]) : "r"(addr));
}
__device__ __forceinline__ void mma16816(float* c, const uint32_t* a, uint32_t b0, uint32_t b1) {
    asm volatile("mma.sync.aligned.m16n8k16.row.col.f32.f16.f16.f32 "
                 "{%0,%1,%2,%3}, {%4,%5,%6,%7}, {%8,%9}, {%0,%1,%2,%3};"
                 : "+f"(c[0]), "+f"(c[1]), "+f"(c[2]), "+f"(c[3])
                 : "r"(a[0]), "r"(a[1]), "r"(a[2]), "r"(a[3]), "r"(b0), "r"(b1));
}

// ---------------------------------------------------------------------------
// Prep kernels (unchanged)
// ---------------------------------------------------------------------------
__global__ __launch_bounds__(256)
void wprep_kernel(const float* __restrict__ Zw, const float* __restrict__ lx,
                  const float* __restrict__ lw)
{
    const int idx = blockIdx.x * 256 + threadIdx.x;
    const int k   = idx / (V_DIM / 4);
    const int v4  = idx % (V_DIM / 4);
    const float coeff = __ldg(lx + k) * __ldg(lw + k);
    float4 w = *reinterpret_cast<const float4*>(Zw + (size_t)k * V_DIM + v4 * 4);
    __half h[4];
    h[0] = __float2half(coeff * w.x);
    h[1] = __float2half(coeff * w.y);
    h[2] = __float2half(coeff * w.z);
    h[3] = __float2half(coeff * w.w);
    *reinterpret_cast<uint2*>(g_Wx + (size_t)k * V_DIM + v4 * 4) =
        *reinterpret_cast<uint2*>(h);
}

template <int WHICH>   // 0: x -> g_xh/g_xl, 1: U -> g_Uh/g_Ul
__global__ __launch_bounds__(256)
void split_kernel(const float* __restrict__ src)
{
    __half* hi = (WHICH == 0) ? g_xh : g_Uh;
    __half* lo = (WHICH == 0) ? g_xl : g_Ul;
    const size_t i4 = ((size_t)blockIdx.x * 256 + threadIdx.x) * 4;
    float4 v = *reinterpret_cast<const float4*>(src + i4);
    __half h[4], l[4];
    h[0] = __float2half(v.x); l[0] = __float2half((v.x - __half2float(h[0])) * RES_SCALE);
    h[1] = __float2half(v.y); l[1] = __float2half((v.y - __half2float(h[1])) * RES_SCALE);
    h[2] = __float2half(v.z); l[2] = __float2half((v.z - __half2float(h[2])) * RES_SCALE);
    h[3] = __float2half(v.w); l[3] = __float2half((v.w - __half2float(h[3])) * RES_SCALE);
    *reinterpret_cast<uint2*>(hi + i4) = *reinterpret_cast<uint2*>(h);
    *reinterpret_cast<uint2*>(lo + i4) = *reinterpret_cast<uint2*>(l);
}

// ---------------------------------------------------------------------------
// GEMM tiling: 128(M)x128(N) CTA tile, BK=64, 3-stage cp.async, 2 CTAs/SM.
// 256 threads = 8 warps as 2(m)x4(n), warp tile 64x32.
// ---------------------------------------------------------------------------
#define BKK 64
#define STAGES 3
#define A_ROW_B 144                     // 64 fp16 + 8 pad
#define B_ROW_B 272                     // 128 fp16 + 8 pad (odd * 16B)
#define A_STG (128 * A_ROW_B)           // 18432
#define B_STG (64 * B_ROW_B)            // 17408
#define STG_B (A_STG + B_STG)           // 35840
#define SMEM_MMA (STAGES * STG_B)       // 107520 -> 2 CTAs/SM = 215040
#define NTHREADS 256

// ---------------------------------------------------------------------------
// GEMM1 — scaled-residual 3-pass + quantize -> g_Aq.
// grid (N_TOK/128, D_DIM/128) = (32, 16). K_ext = 3*2048.
// ---------------------------------------------------------------------------
__global__ __launch_bounds__(NTHREADS, 2)
void gemm1_mma_kernel(const float* __restrict__ lx, const float* __restrict__ cb)
{
    extern __shared__ __align__(128) unsigned char sm1[];
    const uint32_t sb = smem_u32(sm1);
    const int tid  = threadIdx.x;
    const int lane = tid & 31;
    const int wid  = tid >> 5;
    const int wm   = wid >> 2;          // 0..1
    const int wn   = wid & 3;           // 0..3
    const int m0   = blockIdx.x * 128;
    const int n0   = blockIdx.y * 128;

    float acc[4][4][4];
    #pragma unroll
    for (int mi = 0; mi < 4; ++mi)
        #pragma unroll
        for (int ni = 0; ni < 4; ++ni)
            #pragma unroll
            for (int r = 0; r < 4; ++r) acc[mi][ni][r] = 0.0f;

    auto load_stage = [&](int kt, int slot) {
        const int p  = kt >> 5;            // pass: 0=lh, 1=hl, 2=hh
        const int kb = (kt & 31) * BKK;
        const __half* Ab = (p == 0) ? g_xl : g_xh;
        const __half* Bb = (p == 1) ? g_Ul : g_Uh;
        const uint32_t sa  = sb + slot * STG_B;
        const uint32_t sbB = sa + A_STG;
        #pragma unroll
        for (int i = 0; i < 4; ++i) {                   // A: 1024 chunks
            int cc = tid + i * NTHREADS;
            int row = cc >> 3, col = (cc & 7) * 8;
            cp16(sa + row * A_ROW_B + col * 2,
                 Ab + (size_t)(m0 + row) * D_DIM + kb + col);
        }
        #pragma unroll
        for (int i = 0; i < 4; ++i) {                   // B: 1024 chunks
            int cc = tid + i * NTHREADS;
            int row = cc >> 4, col = (cc & 15) * 8;
            cp16(sbB + row * B_ROW_B + col * 2,
                 Bb + (size_t)(kb + row) * D_DIM + n0 + col);
        }
        CP_COMMIT();
    };

    const int KT = 3 * (D_DIM / BKK);    // 96
    load_stage(0, 0);
    load_stage(1, 1);

    const int a_row_l = wm * 64 + (lane & 15);
    const int a_k_l   = (lane >> 4) * 8;
    const int b_row_l = (lane & 7) + ((lane >> 3) & 1) * 8;
    const int b_col_l = wn * 32 + ((lane >> 4) & 1) * 8;

    int slot = 0;
    for (int kt = 0; kt < KT; ++kt) {
        if (kt == 64) {   // acc holds 2^11*(lh+hl): rescale once before hh
            #pragma unroll
            for (int mi = 0; mi < 4; ++mi)
                #pragma unroll
                for (int ni = 0; ni < 4; ++ni)
                    #pragma unroll
                    for (int r = 0; r < 4; ++r)
                        acc[mi][ni][r] *= RES_INV;
        }

        CP_WAIT1();
        __syncthreads();
        const uint32_t sa  = sb + slot * STG_B;
        const uint32_t sbb = sa + A_STG;

        #pragma unroll
        for (int ks = 0; ks < 4; ++ks) {
            uint32_t a[4][4], b[2][4];
            #pragma unroll
            for (int mi = 0; mi < 4; ++mi)
                ldsm4(a[mi], sa + (a_row_l + mi * 16) * A_ROW_B + (a_k_l + ks * 16) * 2);
            #pragma unroll
            for (int ni2 = 0; ni2 < 2; ++ni2)
                ldsm4t(b[ni2], sbb + (b_row_l + ks * 16) * B_ROW_B + (b_col_l + ni2 * 16) * 2);
            #pragma unroll
            for (int mi = 0; mi < 4; ++mi)
                #pragma unroll
                for (int ni = 0; ni < 4; ++ni)
                    mma16816(acc[mi][ni], a[mi], b[ni >> 1][2 * (ni & 1)],
                             b[ni >> 1][2 * (ni & 1) + 1]);
        }

        if (kt + 2 < KT) load_stage(kt + 2, (slot + 2) % STAGES);
        else CP_COMMIT();
        slot = (slot + 1) % STAGES;
    }

    // epilogue: quantize s -> codebook value (tie -> lower index), store fp16
    float c[16];
    #pragma unroll
    for (int t = 0; t < 16; ++t) c[t] = cb[t];

    #pragma unroll
    for (int ni = 0; ni < 4; ++ni) {
        const int c0 = n0 + wn * 32 + ni * 8 + (lane & 3) * 2;
        float l0 = lx[c0], l1 = lx[c0 + 1];
        float s0 = (fabsf(l0) < 1e-8f) ? 1e-8f : l0;
        float s1 = (fabsf(l1) < 1e-8f) ? 1e-8f : l1;
        #pragma unroll
        for (int mi = 0; mi < 4; ++mi) {
            const int r0 = m0 + wm * 64 + mi * 16 + (lane >> 2);
            #pragma unroll
            for (int half_i = 0; half_i < 2; ++half_i) {
                float z0 = acc[mi][ni][2 * half_i]     / s0;
                float z1 = acc[mi][ni][2 * half_i + 1] / s1;
                float q0 = c[0], q1 = c[0];
                #pragma unroll
                for (int t = 0; t < 15; ++t) {
                    float mid = 0.5f * (c[t] + c[t + 1]);
                    q0 = (z0 > mid) ? c[t + 1] : q0;
                    q1 = (z1 > mid) ? c[t + 1] : q1;
                }
                __half2 hv = __halves2half2(__float2half(q0), __float2half(q1));
                *reinterpret_cast<uint32_t*>(
                    &g_Aq[(size_t)(r0 + 8 * half_i) * D_DIM + c0]) =
                    *reinterpret_cast<uint32_t*>(&hv);
            }
        }
    }
}

// ---------------------------------------------------------------------------
// GEMM2 — logits = A @ Wh. grid (N_TOK/128, V_DIM/128). K = 2048.
// ---------------------------------------------------------------------------
__global__ __launch_bounds__(NTHREADS, 2)
void gemm2_mma_kernel(float* __restrict__ C)
{
    extern __shared__ __align__(128) unsigned char sm2[];
    const uint32_t sb = smem_u32(sm2);
    const int tid  = threadIdx.x;
    const int lane = tid & 31;
    const int wid  = tid >> 5;
    const int wm   = wid >> 2;
    const int wn   = wid & 3;
    const int m0   = blockIdx.x * 128;
    const int n0   = blockIdx.y * 128;

    float acc[4][4][4];
    #pragma unroll
    for (int mi = 0; mi < 4; ++mi)
        #pragma unroll
        for (int ni = 0; ni < 4; ++ni)
            #pragma unroll
            for (int r = 0; r < 4; ++r) acc[mi][ni][r] = 0.0f;

    auto load_stage = [&](int kt, int slot) {
        const int kb = kt * BKK;
        const uint32_t sa  = sb + slot * STG_B;
        const uint32_t sbB = sa + A_STG;
        #pragma unroll
        for (int i = 0; i < 4; ++i) {
            int cc = tid + i * NTHREADS;
            int row = cc >> 3, col = (cc & 7) * 8;
            cp16(sa + row * A_ROW_B + col * 2,
                 g_Aq + (size_t)(m0 + row) * D_DIM + kb + col);
        }
        #pragma unroll
        for (int i = 0; i < 4; ++i) {
            int cc = tid + i * NTHREADS;
            int row = cc >> 4, col = (cc & 15) * 8;
            cp16(sbB + row * B_ROW_B + col * 2,
                 g_Wx + (size_t)(kb + row) * V_DIM + n0 + col);
        }
        CP_COMMIT();
    };

    const int KT = D_DIM / BKK;     // 32
    load_stage(0, 0);
    load_stage(1, 1);

    const int a_row_l = wm * 64 + (lane & 15);
    const int a_k_l   = (lane >> 4) * 8;
    const int b_row_l = (lane & 7) + ((lane >> 3) & 1) * 8;
    const int b_col_l = wn * 32 + ((lane >> 4) & 1) * 8;

    int slot = 0;
    for (int kt = 0; kt < KT; ++kt) {
        CP_WAIT1();
        __syncthreads();
        const uint32_t sa  = sb + slot * STG_B;
        const uint32_t sbb = sa + A_STG;

        #pragma unroll
        for (int ks = 0; ks < 4; ++ks) {
            uint32_t a[4][4], b[2][4];
            #pragma unroll
            for (int mi = 0; mi < 4; ++mi)
                ldsm4(a[mi], sa + (a_row_l + mi * 16) * A_ROW_B + (a_k_l + ks * 16) * 2);
            #pragma unroll
            for (int ni2 = 0; ni2 < 2; ++ni2)
                ldsm4t(b[ni2], sbb + (b_row_l + ks * 16) * B_ROW_B + (b_col_l + ni2 * 16) * 2);
            #pragma unroll
            for (int mi = 0; mi < 4; ++mi)
                #pragma unroll
                for (int ni = 0; ni < 4; ++ni)
                    mma16816(acc[mi][ni], a[mi], b[ni >> 1][2 * (ni & 1)],
                             b[ni >> 1][2 * (ni & 1) + 1]);
        }

        if (kt + 2 < KT) load_stage(kt + 2, (slot + 2) % STAGES);
        else CP_COMMIT();
        slot = (slot + 1) % STAGES;
    }

    #pragma unroll
    for (int mi = 0; mi < 4; ++mi) {
        const int row = m0 + wm * 64 + mi * 16 + (lane >> 2);
        #pragma unroll
        for (int ni = 0; ni < 4; ++ni) {
            const int col = n0 + wn * 32 + ni * 8 + (lane & 3) * 2;
            float2 v0 = make_float2(acc[mi][ni][0], acc[mi][ni][1]);
            float2 v1 = make_float2(acc[mi][ni][2], acc[mi][ni][3]);
            *reinterpret_cast<float2*>(C + (size_t)row * V_DIM + col) = v0;
            *reinterpret_cast<float2*>(C + (size_t)(row + 8) * V_DIM + col) = v1;
        }
    }
}

// ---------------------------------------------------------------------------
extern "C" void kernel_launch(void* const* d_in, const int* in_sizes, int n_in,
                              void* d_out, int out_size)
{
    const float* x  = (const float*)d_in[0];
    const float* U  = (const float*)d_in[1];
    const float* lx = (const float*)d_in[2];
    const float* lw = (const float*)d_in[3];
    const float* Zw = (const float*)d_in[4];
    const float* cb = (const float*)d_in[5];
    float* out = (float*)d_out;

    cudaFuncSetAttribute(gemm1_mma_kernel,
                         cudaFuncAttributeMaxDynamicSharedMemorySize, SMEM_MMA);
    cudaFuncSetAttribute(gemm2_mma_kernel,
                         cudaFuncAttributeMaxDynamicSharedMemorySize, SMEM_MMA);

    // prep
    wprep_kernel<<<(D_DIM * V_DIM / 4) / 256, 256>>>(Zw, lx, lw);
    split_kernel<0><<<((size_t)N_TOK * D_DIM / 4) / 256, 256>>>(x);
    split_kernel<1><<<((size_t)D_DIM * D_DIM / 4) / 256, 256>>>(U);

    // GEMM1 (scaled-residual 3-pass) + quantize -> g_Aq
    gemm1_mma_kernel<<<dim3(N_TOK / 128, D_DIM / 128), NTHREADS, SMEM_MMA>>>(lx, cb);

    // GEMM2 -> logits
    gemm2_mma_kernel<<<dim3(N_TOK / 128, V_DIM / 128), NTHREADS, SMEM_MMA>>>(out);
}